// round 6
// baseline (speedup 1.0000x reference)
#include <cuda_runtime.h>
#include <cstdint>

// Problem constants (from reference)
#define BB 8
#define TT 512
#define SS 512
#define HH 768
#define VOCAB 32110

// One block per (b, t) row of the output.
//   out layout: [ optional p_gen prefix (B*T floats) | logits (B*T*VOCAB floats) ]
// Block tasks:
//   1) zero-fill its own logits row (float2 stores; row stride is 8B aligned)
//   2) compute p_gen[b,t] = sigmoid(dec·w[:H] + seq·w[H:] + b)
//   3) after barrier, scatter-add its 512 attn weights into its own row
__global__ __launch_bounds__(256, 8)
void copymech_kernel(const float* __restrict__ dec,        // [B,T,H]
                     const float* __restrict__ seq,        // [B,T,H]
                     const float* __restrict__ attn,       // [B,T,S]
                     const int*   __restrict__ ids_raw,    // [B,S] int32 OR int64 (detected)
                     const float* __restrict__ w,          // [2H]
                     const float* __restrict__ bias,       // [1]
                     float* __restrict__ out,
                     long long logits_off)                 // elems before logits block
{
    const int bt  = blockIdx.x;          // 0 .. B*T-1
    const int b   = bt / TT;
    const int tid = threadIdx.x;         // 256 threads

    float* __restrict__ logits_row = out + logits_off + (size_t)bt * VOCAB;

    // ---- 0a) detect ids dtype. Both layouts have >= 4096 int32 words.
    //          If int64 (LE), every odd word is 0 (ids < 2^31). Check the
    //          odd words of the first 64: all zero => int64.
    int oddor = 0;
    #pragma unroll
    for (int i = 1; i < 64; i += 2) oddor |= ids_raw[i];
    const bool is64 = (oddor == 0);

    // ---- 0b) front-batch the scatter operands (2 per thread) so their DRAM
    //          latency overlaps the zero-fill store stream below ----
    const float* __restrict__ arow = attn + (size_t)bt * SS;
    const int s0 = tid;            // SS=512, blockDim=256 -> exactly 2 each
    const int s1 = tid + 256;
    const float a0 = arow[s0];
    const float a1 = arow[s1];
    int v0, v1;
    if (is64) {
        const long long* idrow = (const long long*)ids_raw + (size_t)b * SS;
        v0 = (int)idrow[s0];
        v1 = (int)idrow[s1];
    } else {
        const int* idrow = ids_raw + (size_t)b * SS;
        v0 = idrow[s0];
        v1 = idrow[s1];
    }

    // ---- 1) zero the row (VOCAB = 32110 is even; row base is 8B-aligned) ----
    float2* __restrict__ row2 = reinterpret_cast<float2*>(logits_row);
    const int n2 = VOCAB / 2;            // 16055
    #pragma unroll 4
    for (int i = tid; i < n2; i += 256) {
        row2[i] = make_float2(0.0f, 0.0f);
    }

    // ---- 2) p_gen dot product (H=768 per tensor) ----
    const float* __restrict__ drow = dec + (size_t)bt * HH;
    const float* __restrict__ srow = seq + (size_t)bt * HH;
    float acc = 0.0f;
    #pragma unroll
    for (int i = tid; i < HH; i += 256) {
        acc = fmaf(drow[i], w[i], acc);
        acc = fmaf(srow[i], w[HH + i], acc);
    }
    // warp reduce
    #pragma unroll
    for (int o = 16; o > 0; o >>= 1)
        acc += __shfl_xor_sync(0xFFFFFFFFu, acc, o);

    __shared__ float warp_sums[8];
    if ((tid & 31) == 0) warp_sums[tid >> 5] = acc;

    // This barrier ALSO orders the zero-fill stores before the atomic scatter.
    __syncthreads();

    if (tid == 0 && logits_off >= BB * TT) {
        float s = bias[0];
        #pragma unroll
        for (int i = 0; i < 8; i++) s += warp_sums[i];
        out[bt] = 1.0f / (1.0f + expf(-s));
    }

    // ---- 3) scatter-add attn[b,t,:] into this block's own logits row ----
    //         (bound-checked: any dtype misread degrades to rel_err, not a fault)
    if ((unsigned)v0 < VOCAB) atomicAdd(&logits_row[v0], a0);
    if ((unsigned)v1 < VOCAB) atomicAdd(&logits_row[v1], a1);
}

extern "C" void kernel_launch(void* const* d_in, const int* in_sizes, int n_in,
                              void* d_out, int out_size)
{
    const float* dec  = (const float*)d_in[0];
    const float* seq  = (const float*)d_in[1];
    const float* attn = (const float*)d_in[2];
    const int*   ids  = (const int*)d_in[3];
    const float* w    = (const float*)d_in[4];
    const float* bias = (const float*)d_in[5];
    float*       out  = (float*)d_out;

    // Logits occupy the trailing B*T*VOCAB elements; any prefix is p_gen.
    const long long total_logits = (long long)BB * TT * VOCAB;
    long long logits_off = (long long)out_size - total_logits;
    if (logits_off < 0) logits_off = 0;   // defensive; should not happen

    copymech_kernel<<<BB * TT, 256>>>(dec, seq, attn, ids, w, bias, out, logits_off);
}

// round 13
// speedup vs baseline: 1.0245x; 1.0245x over previous
#include <cuda_runtime.h>
#include <cstdint>

// Problem constants (from reference)
#define BB 8
#define TT 512
#define SS 512
#define HH 768
#define VOCAB 32110

// One block per (b, t) row of the output.
//   out layout: [ optional p_gen prefix (B*T floats) | logits (B*T*VOCAB floats) ]
// Block tasks:
//   1) zero-fill its own logits row with STG.128 (2-float pro/epilogue handles
//      the alternating 8-mod-16 row base: stride = 32110*4 B)
//   2) compute p_gen[b,t] = sigmoid(dec·w[:H] + seq·w[H:] + b)
//   3) after barrier, scatter-add its 512 attn weights into its own row
__global__ __launch_bounds__(256, 8)
void copymech_kernel(const float* __restrict__ dec,        // [B,T,H]
                     const float* __restrict__ seq,        // [B,T,H]
                     const float* __restrict__ attn,       // [B,T,S]
                     const int*   __restrict__ ids_raw,    // [B,S] int32 OR int64 (detected)
                     const float* __restrict__ w,          // [2H]
                     const float* __restrict__ bias,       // [1]
                     float* __restrict__ out,
                     long long logits_off)                 // elems before logits block
{
    const int bt  = blockIdx.x;          // 0 .. B*T-1
    const int b   = bt / TT;
    const int tid = threadIdx.x;         // 256 threads

    float* __restrict__ logits_row = out + logits_off + (size_t)bt * VOCAB;

    // ---- 0a) detect ids dtype. If int64 (LE), every odd word is 0 (ids < 2^31).
    int oddor = 0;
    #pragma unroll
    for (int i = 1; i < 64; i += 2) oddor |= ids_raw[i];
    const bool is64 = (oddor == 0);

    // ---- 0b) front-batch the scatter operands (2 per thread) so their DRAM
    //          latency overlaps the zero-fill store stream below ----
    const float* __restrict__ arow = attn + (size_t)bt * SS;
    const int s0 = tid;            // SS=512, blockDim=256 -> exactly 2 each
    const int s1 = tid + 256;
    const float a0 = arow[s0];
    const float a1 = arow[s1];
    int v0, v1;
    if (is64) {
        const long long* idrow = (const long long*)ids_raw + (size_t)b * SS;
        v0 = (int)idrow[s0];
        v1 = (int)idrow[s1];
    } else {
        const int* idrow = ids_raw + (size_t)b * SS;
        v0 = idrow[s0];
        v1 = idrow[s1];
    }

    // ---- 1) zero the row with float4 stores ----
    // Row base is 8-mod-16 for odd bt (stride 128440 B). Peel 2 floats at the
    // front (misaligned case) or the back (aligned case); middle = 8027 float4.
    const bool mis = (((uintptr_t)logits_row) & 15u) != 0;
    if (tid == 0) {
        float2* edge = reinterpret_cast<float2*>(mis ? logits_row
                                                     : logits_row + (VOCAB - 2));
        *edge = make_float2(0.0f, 0.0f);
    }
    float4* __restrict__ row4 =
        reinterpret_cast<float4*>(logits_row + (mis ? 2 : 0));
    const float4 z4 = make_float4(0.0f, 0.0f, 0.0f, 0.0f);
    const int n4 = (VOCAB - 2) / 4;      // 8027
    #pragma unroll 4
    for (int i = tid; i < n4; i += 256) {
        row4[i] = z4;
    }

    // ---- 2) p_gen dot product (H=768 per tensor) ----
    const float* __restrict__ drow = dec + (size_t)bt * HH;
    const float* __restrict__ srow = seq + (size_t)bt * HH;
    float acc = 0.0f;
    #pragma unroll
    for (int i = tid; i < HH; i += 256) {
        acc = fmaf(drow[i], w[i], acc);
        acc = fmaf(srow[i], w[HH + i], acc);
    }
    // warp reduce
    #pragma unroll
    for (int o = 16; o > 0; o >>= 1)
        acc += __shfl_xor_sync(0xFFFFFFFFu, acc, o);

    __shared__ float warp_sums[8];
    if ((tid & 31) == 0) warp_sums[tid >> 5] = acc;

    // This barrier ALSO orders the zero-fill stores before the atomic scatter.
    __syncthreads();

    if (tid == 0 && logits_off >= BB * TT) {
        float s = bias[0];
        #pragma unroll
        for (int i = 0; i < 8; i++) s += warp_sums[i];
        out[bt] = 1.0f / (1.0f + expf(-s));
    }

    // ---- 3) scatter-add attn[b,t,:] into this block's own logits row ----
    if ((unsigned)v0 < VOCAB) atomicAdd(&logits_row[v0], a0);
    if ((unsigned)v1 < VOCAB) atomicAdd(&logits_row[v1], a1);
}

extern "C" void kernel_launch(void* const* d_in, const int* in_sizes, int n_in,
                              void* d_out, int out_size)
{
    const float* dec  = (const float*)d_in[0];
    const float* seq  = (const float*)d_in[1];
    const float* attn = (const float*)d_in[2];
    const int*   ids  = (const int*)d_in[3];
    const float* w    = (const float*)d_in[4];
    const float* bias = (const float*)d_in[5];
    float*       out  = (float*)d_out;

    // Logits occupy the trailing B*T*VOCAB elements; any prefix is p_gen.
    const long long total_logits = (long long)BB * TT * VOCAB;
    long long logits_off = (long long)out_size - total_logits;
    if (logits_off < 0) logits_off = 0;   // defensive; should not happen

    copymech_kernel<<<BB * TT, 256>>>(dec, seq, attn, ids, w, bias, out, logits_off);
}